// round 2
// baseline (speedup 1.0000x reference)
#include <cuda_runtime.h>

#define NB 2
#define DD 160
#define HH 192
#define WW 224
#define SLICE (HH*WW)          // 43008
#define VOL   (DD*SLICE)       // 6881280

#define TX 32
#define TY 16
#define DSEG 40
#define NSEG (DD/DSEG)         // 4

#define W0 0.05448868454964294f
#define W1 0.24420134200323332f
#define W2 0.40261994689424753f

__device__ double g_sum[2];

// ---------------------------------------------------------------------------
// Fully fused LNCC: per block, a 32x16 (x,y) tile and a 40-deep D segment.
// Slide along D: stage raw slice -> W-blur (products on the fly) -> H-blur
// (2 stacked y-points per thread) -> D-blur in a register shift-register ->
// LNCC + masked reduction. No global intermediates.
// ---------------------------------------------------------------------------
__global__ void __launch_bounds__(256, 2) lncc_fused(const float* __restrict__ I,
                                                     const float* __restrict__ J,
                                                     const float* __restrict__ M)
{
    __shared__ float sa[20][36];        // raw I slice with halo
    __shared__ float sb[20][36];        // raw J slice with halo
    __shared__ float sw[5][20][32];     // W-blurred channels, y-halo rows
    __shared__ float rbuf[16];

    const int tid = threadIdx.x;
    const int x   = tid & 31;
    const int y0  = (tid >> 5) * 2;     // 0,2,...,14 ; thread owns rows y0, y0+1

    const int bz  = blockIdx.z;
    const int n   = bz / NSEG;
    const int d0  = (bz - n * NSEG) * DSEG;
    const int gx0 = blockIdx.x * TX;
    const int gy0 = blockIdx.y * TY;

    const float* __restrict__ Ibase = I + (size_t)n * VOL;
    const float* __restrict__ Jbase = J + (size_t)n * VOL;
    const float* __restrict__ Mbase = M + (size_t)n * VOL;

    // D-axis shift register: A[j] accumulates output depth od = s + 2 - j.
    float A[5][5][2];
    #pragma unroll
    for (int j = 0; j < 5; j++)
        #pragma unroll
        for (int c = 0; c < 5; c++) {
            A[j][c][0] = 0.f; A[j][c][1] = 0.f;
        }

    float sl = 0.f, sm = 0.f;
    const float wD[5] = {W0, W1, W2, W1, W0};

    for (int s = d0 - 2; s <= d0 + DSEG + 1; ++s) {
        const bool zs = (s < 0) || (s >= DD);

        // ---- stage raw slice with halo (zero padding) ----
        if (!zs) {
            const float* __restrict__ Ip = Ibase + (size_t)s * SLICE;
            const float* __restrict__ Jp = Jbase + (size_t)s * SLICE;
            for (int i = tid; i < 20 * 36; i += 256) {
                int r  = i / 36;
                int c  = i - r * 36;
                int gy = gy0 + r - 2;
                int gx = gx0 + c - 2;
                float a = 0.f, b = 0.f;
                if ((unsigned)gy < HH && (unsigned)gx < WW) {
                    int o = gy * WW + gx;
                    a = Ip[o];
                    b = Jp[o];
                }
                sa[r][c] = a;
                sb[r][c] = b;
            }
        }
        __syncthreads();

        // ---- W blur of the 5 channels, products formed on the fly ----
        if (!zs) {
            for (int i = tid; i < 20 * 32; i += 256) {
                int r  = i >> 5;
                int xx = i & 31;
                float a0 = sa[r][xx],   a1 = sa[r][xx+1], a2 = sa[r][xx+2],
                      a3 = sa[r][xx+3], a4 = sa[r][xx+4];
                float b0 = sb[r][xx],   b1 = sb[r][xx+1], b2 = sb[r][xx+2],
                      b3 = sb[r][xx+3], b4 = sb[r][xx+4];
                sw[0][r][xx] = W0*(a0+a4) + W1*(a1+a3) + W2*a2;
                sw[1][r][xx] = W0*(b0+b4) + W1*(b1+b3) + W2*b2;
                sw[2][r][xx] = W0*(a0*b0 + a4*b4) + W1*(a1*b1 + a3*b3) + W2*(a2*b2);
                sw[3][r][xx] = W0*(a0*a0 + a4*a4) + W1*(a1*a1 + a3*a3) + W2*(a2*a2);
                sw[4][r][xx] = W0*(b0*b0 + b4*b4) + W1*(b1*b1 + b3*b3) + W2*(b2*b2);
            }
        }
        __syncthreads();

        // ---- H blur (2 stacked rows per thread) + D shift-register update ----
        if (!zs) {
            float v[5][2];
            #pragma unroll
            for (int c = 0; c < 5; c++) {
                float t0 = sw[c][y0  ][x], t1 = sw[c][y0+1][x], t2 = sw[c][y0+2][x],
                      t3 = sw[c][y0+3][x], t4 = sw[c][y0+4][x], t5 = sw[c][y0+5][x];
                v[c][0] = W0*(t0+t4) + W1*(t1+t3) + W2*t2;
                v[c][1] = W0*(t1+t5) + W1*(t2+t4) + W2*t3;
            }
            #pragma unroll
            for (int j = 0; j < 5; j++)
                #pragma unroll
                for (int c = 0; c < 5; c++) {
                    A[j][c][0] = fmaf(wD[j], v[c][0], A[j][c][0]);
                    A[j][c][1] = fmaf(wD[j], v[c][1], A[j][c][1]);
                }
        }

        // ---- emit output depth od = s - 2 (A[4] is complete) ----
        const int od = s - 2;
        if (od >= d0) {
            #pragma unroll
            for (int p = 0; p < 2; p++) {
                float bI  = A[4][0][p], bJ  = A[4][1][p];
                float bIJ = A[4][2][p], bII = A[4][3][p], bJJ = A[4][4][p];
                float cross = bIJ - bI * bJ;
                float varI  = fmaxf(bII - bI * bI, 0.f) + 1e-5f;
                float varJ  = fmaxf(bJJ - bJ * bJ, 0.f) + 1e-5f;
                float lncc  = 1.f - cross * rsqrtf(varI * varJ);
                float m = Mbase[(size_t)od * SLICE + (size_t)(gy0 + y0 + p) * WW + gx0 + x];
                sl += lncc * m;
                sm += m;
            }
        }

        // ---- shift the D accumulator ----
        #pragma unroll
        for (int j = 4; j > 0; j--)
            #pragma unroll
            for (int c = 0; c < 5; c++) {
                A[j][c][0] = A[j-1][c][0];
                A[j][c][1] = A[j-1][c][1];
            }
        #pragma unroll
        for (int c = 0; c < 5; c++) {
            A[0][c][0] = 0.f; A[0][c][1] = 0.f;
        }
    }

    // ---- block reduction ----
    #pragma unroll
    for (int o = 16; o > 0; o >>= 1) {
        sl += __shfl_down_sync(0xFFFFFFFFu, sl, o);
        sm += __shfl_down_sync(0xFFFFFFFFu, sm, o);
    }
    if ((tid & 31) == 0) {
        rbuf[tid >> 5]     = sl;
        rbuf[8 + (tid >> 5)] = sm;
    }
    __syncthreads();
    if (tid == 0) {
        float tl = 0.f, tm = 0.f;
        #pragma unroll
        for (int i = 0; i < 8; i++) { tl += rbuf[i]; tm += rbuf[8 + i]; }
        atomicAdd(&g_sum[0], (double)tl);
        atomicAdd(&g_sum[1], (double)tm);
    }
}

__global__ void lncc_init()
{
    g_sum[0] = 0.0;
    g_sum[1] = 0.0;
}

__global__ void lncc_final(float* __restrict__ out)
{
    out[0] = (float)(g_sum[0] / (g_sum[1] + 1e-8));
}

// ---------------------------------------------------------------------------

extern "C" void kernel_launch(void* const* d_in, const int* in_sizes, int n_in,
                              void* d_out, int out_size)
{
    const float* A = (const float*)d_in[0];  // image_A
    const float* B = (const float*)d_in[1];  // image_B
    const float* M = (const float*)d_in[2];  // mask_A
    float* out = (float*)d_out;

    lncc_init<<<1, 1>>>();

    dim3 g(WW / TX, HH / TY, NB * NSEG);     // (7, 12, 8) = 672 blocks
    lncc_fused<<<g, 256>>>(A, B, M);

    lncc_final<<<1, 1>>>(out);
}

// round 3
// speedup vs baseline: 2.2090x; 2.2090x over previous
#include <cuda_runtime.h>
#include <cuda_fp16.h>

#define NB 2
#define DD 160
#define HH 192
#define WW 224
#define SLICE (HH*WW)          // 43008
#define VOL   (DD*SLICE)       // 6881280
#define TOT   (NB*VOL)         // 13762560

#define W0 0.05448868454964294f
#define W1 0.24420134200323332f
#define W2 0.40261994689424753f

// 137 MB fp16 scratch for the 5 W+H-blurred channels, channel-major planes.
__device__ __half  g_mid[5u * TOT];
__device__ double  g_sum[2];

// ---------------------------------------------------------------------------
// Kernel A: per (n,d) slice, fused W+H blur of the 5 channels.
// Raw a,b staged once; products formed on the fly in the W pass.
// H pass: each thread owns 4 stacked y-outputs (8 rows serve 4 outputs).
// Output stored fp16.
// ---------------------------------------------------------------------------
__global__ void __launch_bounds__(256) lncc_blur_wh(const float* __restrict__ I,
                                                    const float* __restrict__ J)
{
    __shared__ float sa[36][36];
    __shared__ float sb[36][36];
    __shared__ float sw[5][36][32];

    const int tid = threadIdx.x;
    const int nd  = blockIdx.z;                 // n*DD + d
    const int gx0 = blockIdx.x * 32;
    const int gy0 = blockIdx.y * 32;

    const float* __restrict__ Ib = I + (size_t)nd * SLICE;
    const float* __restrict__ Jb = J + (size_t)nd * SLICE;

    // Stage raw slice with 2-halo (zero padding).
    for (int i = tid; i < 36 * 36; i += 256) {
        int ly = i / 36, lx = i - ly * 36;
        int gy = gy0 + ly - 2, gx = gx0 + lx - 2;
        float a = 0.f, b = 0.f;
        if ((unsigned)gy < HH && (unsigned)gx < WW) {
            int o = gy * WW + gx;
            a = Ib[o];
            b = Jb[o];
        }
        sa[ly][lx] = a;
        sb[ly][lx] = b;
    }
    __syncthreads();

    // W blur: 36 rows x 32 cols, 5 channels with on-the-fly products.
    for (int i = tid; i < 36 * 32; i += 256) {
        int r  = i >> 5;
        int xx = i & 31;
        float a0 = sa[r][xx],   a1 = sa[r][xx+1], a2 = sa[r][xx+2],
              a3 = sa[r][xx+3], a4 = sa[r][xx+4];
        float b0 = sb[r][xx],   b1 = sb[r][xx+1], b2 = sb[r][xx+2],
              b3 = sb[r][xx+3], b4 = sb[r][xx+4];
        sw[0][r][xx] = W0*(a0+a4)       + W1*(a1+a3)       + W2*a2;
        sw[1][r][xx] = W0*(b0+b4)       + W1*(b1+b3)       + W2*b2;
        sw[2][r][xx] = W0*(a0*b0+a4*b4) + W1*(a1*b1+a3*b3) + W2*(a2*b2);
        sw[3][r][xx] = W0*(a0*a0+a4*a4) + W1*(a1*a1+a3*a3) + W2*(a2*a2);
        sw[4][r][xx] = W0*(b0*b0+b4*b4) + W1*(b1*b1+b3*b3) + W2*(b2*b2);
    }
    __syncthreads();

    // H blur: thread owns x = tid&31, y-outputs y0..y0+3.
    const int x  = tid & 31;
    const int y0 = (tid >> 5) * 4;
    const size_t obase = (size_t)nd * SLICE;

    #pragma unroll
    for (int c = 0; c < 5; c++) {
        float t[8];
        #pragma unroll
        for (int r = 0; r < 8; r++) t[r] = sw[c][y0 + r][x];
        #pragma unroll
        for (int k = 0; k < 4; k++) {
            float s = W0*(t[k] + t[k+4]) + W1*(t[k+1] + t[k+3]) + W2*t[k+2];
            g_mid[(size_t)c * TOT + obase + (size_t)(gy0 + y0 + k) * WW + gx0 + x]
                = __float2half_rn(s);
        }
    }
}

// ---------------------------------------------------------------------------
// Kernel B: D-blur of fp16 mid (4 d-outputs x 4 x-voxels per thread; 8 tap
// slices shared across the 4 outputs), LNCC + masked reduction.
// ---------------------------------------------------------------------------
#define P4 (SLICE/4)           // 10752
#define DG (DD/4)              // 40

__global__ void __launch_bounds__(256) lncc_blur_d_reduce(const float* __restrict__ M)
{
    const int t   = blockIdx.x * 256 + threadIdx.x;   // < NB*DG*P4
    const int n   = t / (DG * P4);
    const int rem = t - n * (DG * P4);
    const int dg  = rem / P4;
    const int p4  = rem - dg * P4;
    const int d0  = dg * 4;
    const int p   = p4 * 4;

    const float wD[5] = {W0, W1, W2, W1, W0};

    float acc[5][4][4];
    #pragma unroll
    for (int c = 0; c < 5; c++)
        #pragma unroll
        for (int k = 0; k < 4; k++) {
            acc[c][k][0] = acc[c][k][1] = acc[c][k][2] = acc[c][k][3] = 0.f;
        }

    const size_t pbase = (size_t)n * VOL + p;

    #pragma unroll
    for (int c = 0; c < 5; c++) {
        const __half* __restrict__ ch = g_mid + (size_t)c * TOT + pbase;
        #pragma unroll
        for (int ss = 0; ss < 8; ss++) {
            const int s = d0 + ss - 2;
            float f0 = 0.f, f1 = 0.f, f2 = 0.f, f3 = 0.f;
            if ((unsigned)s < DD) {
                const uint2 raw = *reinterpret_cast<const uint2*>(ch + (size_t)s * SLICE);
                const __half2 h01 = *reinterpret_cast<const __half2*>(&raw.x);
                const __half2 h23 = *reinterpret_cast<const __half2*>(&raw.y);
                const float2 f01 = __half22float2(h01);
                const float2 f23 = __half22float2(h23);
                f0 = f01.x; f1 = f01.y; f2 = f23.x; f3 = f23.y;
            }
            #pragma unroll
            for (int k = 0; k < 4; k++) {
                const int j = ss - k;
                if (j >= 0 && j <= 4) {
                    acc[c][k][0] = fmaf(wD[j], f0, acc[c][k][0]);
                    acc[c][k][1] = fmaf(wD[j], f1, acc[c][k][1]);
                    acc[c][k][2] = fmaf(wD[j], f2, acc[c][k][2]);
                    acc[c][k][3] = fmaf(wD[j], f3, acc[c][k][3]);
                }
            }
        }
    }

    float sl = 0.f, sm = 0.f;
    #pragma unroll
    for (int k = 0; k < 4; k++) {
        const float4 mk = *reinterpret_cast<const float4*>(
            M + pbase + (size_t)(d0 + k) * SLICE);
        const float mv[4] = {mk.x, mk.y, mk.z, mk.w};
        #pragma unroll
        for (int v = 0; v < 4; v++) {
            float bI  = acc[0][k][v], bJ  = acc[1][k][v];
            float bIJ = acc[2][k][v], bII = acc[3][k][v], bJJ = acc[4][k][v];
            float cross = bIJ - bI * bJ;
            float varI  = fmaxf(bII - bI * bI, 0.f) + 1e-5f;
            float varJ  = fmaxf(bJJ - bJ * bJ, 0.f) + 1e-5f;
            float lncc  = 1.f - cross * rsqrtf(varI * varJ);
            sl += lncc * mv[v];
            sm += mv[v];
        }
    }

    // Block reduction
    #pragma unroll
    for (int o = 16; o > 0; o >>= 1) {
        sl += __shfl_down_sync(0xFFFFFFFFu, sl, o);
        sm += __shfl_down_sync(0xFFFFFFFFu, sm, o);
    }
    __shared__ float rl[8], rm[8];
    const int lane = threadIdx.x & 31, wid = threadIdx.x >> 5;
    if (lane == 0) { rl[wid] = sl; rm[wid] = sm; }
    __syncthreads();
    if (threadIdx.x == 0) {
        float tl = 0.f, tm = 0.f;
        #pragma unroll
        for (int i = 0; i < 8; i++) { tl += rl[i]; tm += rm[i]; }
        atomicAdd(&g_sum[0], (double)tl);
        atomicAdd(&g_sum[1], (double)tm);
    }
}

__global__ void lncc_init()
{
    g_sum[0] = 0.0;
    g_sum[1] = 0.0;
}

__global__ void lncc_final(float* __restrict__ out)
{
    out[0] = (float)(g_sum[0] / (g_sum[1] + 1e-8));
}

// ---------------------------------------------------------------------------

extern "C" void kernel_launch(void* const* d_in, const int* in_sizes, int n_in,
                              void* d_out, int out_size)
{
    const float* A = (const float*)d_in[0];  // image_A
    const float* B = (const float*)d_in[1];  // image_B
    const float* M = (const float*)d_in[2];  // mask_A
    float* out = (float*)d_out;

    lncc_init<<<1, 1>>>();

    dim3 gA(WW / 32, HH / 32, NB * DD);      // (7, 6, 320)
    lncc_blur_wh<<<gA, 256>>>(A, B);

    const int nthr = NB * DG * P4;           // 860160
    lncc_blur_d_reduce<<<nthr / 256, 256>>>(M);

    lncc_final<<<1, 1>>>(out);
}

// round 4
// speedup vs baseline: 2.2682x; 1.0268x over previous
#include <cuda_runtime.h>
#include <cuda_fp16.h>

#define NB 2
#define DD 160
#define HH 192
#define WW 224
#define SLICE (HH*WW)          // 43008
#define VOL   (DD*SLICE)       // 6881280
#define TOT   (NB*VOL)         // 13762560

#define W0 0.05448868454964294f
#define W1 0.24420134200323332f
#define W2 0.40261994689424753f

// fp16 scratch for the 5 W+H-blurred channels (channel-major), as half2.
__device__ __half2   g_mid2[5u * TOT / 2];
__device__ double    g_sum[2];
__device__ unsigned  g_ticket = 0;

// ---------------------------------------------------------------------------
// packed f32x2 helpers (Blackwell sm_103a): full fp32 precision, 2x rate.
// ---------------------------------------------------------------------------
__device__ __forceinline__ float2 add2(float2 a, float2 b) {
    float2 d;
    asm("{\n\t.reg .b64 x,y,w;\n\t"
        "mov.b64 x,{%2,%3};\n\tmov.b64 y,{%4,%5};\n\t"
        "add.rn.f32x2 w,x,y;\n\tmov.b64 {%0,%1},w;\n\t}"
        : "=f"(d.x), "=f"(d.y)
        : "f"(a.x), "f"(a.y), "f"(b.x), "f"(b.y));
    return d;
}
__device__ __forceinline__ float2 mul2(float2 a, float2 b) {
    float2 d;
    asm("{\n\t.reg .b64 x,y,w;\n\t"
        "mov.b64 x,{%2,%3};\n\tmov.b64 y,{%4,%5};\n\t"
        "mul.rn.f32x2 w,x,y;\n\tmov.b64 {%0,%1},w;\n\t}"
        : "=f"(d.x), "=f"(d.y)
        : "f"(a.x), "f"(a.y), "f"(b.x), "f"(b.y));
    return d;
}
__device__ __forceinline__ float2 fma2(float2 a, float2 b, float2 c) {
    float2 d;
    asm("{\n\t.reg .b64 x,y,z,w;\n\t"
        "mov.b64 x,{%2,%3};\n\tmov.b64 y,{%4,%5};\n\tmov.b64 z,{%6,%7};\n\t"
        "fma.rn.f32x2 w,x,y,z;\n\tmov.b64 {%0,%1},w;\n\t}"
        : "=f"(d.x), "=f"(d.y)
        : "f"(a.x), "f"(a.y), "f"(b.x), "f"(b.y), "f"(c.x), "f"(c.y));
    return d;
}

__device__ __forceinline__ float2 blur5(float2 v0, float2 v1, float2 v2,
                                        float2 v3, float2 v4,
                                        float2 w0, float2 w1, float2 w2)
{
    float2 t = add2(v0, v4);
    float2 u = add2(v1, v3);
    float2 s = mul2(w0, t);
    s = fma2(w1, u, s);
    s = fma2(w2, v2, s);
    return s;
}

// ---------------------------------------------------------------------------
// Kernel A: per (n,d) slice, fused W+H blur of the 5 channels, x-pair packed.
// ---------------------------------------------------------------------------
#define SPITCH 19   // stage pitch in pairs (18 used)
#define WPITCH 17   // sw pitch in pairs (16 used)

__global__ void __launch_bounds__(256) lncc_blur_wh(const float* __restrict__ I,
                                                    const float* __restrict__ J)
{
    __shared__ float2 sa[36][SPITCH];
    __shared__ float2 sb[36][SPITCH];
    __shared__ float2 sw[5][36][WPITCH];

    const int tid = threadIdx.x;
    const int nd  = blockIdx.z;                 // n*DD + d
    const int gx0 = blockIdx.x * 32;
    const int gy0 = blockIdx.y * 32;

    if (nd == 0 && blockIdx.x == 0 && blockIdx.y == 0 && tid == 0) {
        g_sum[0] = 0.0;
        g_sum[1] = 0.0;
        g_ticket = 0u;
    }

    const float* __restrict__ Ib = I + (size_t)nd * SLICE;
    const float* __restrict__ Jb = J + (size_t)nd * SLICE;

    const float2 w0 = make_float2(W0, W0);
    const float2 w1 = make_float2(W1, W1);
    const float2 w2 = make_float2(W2, W2);

    // ---- stage raw a,b as x-pairs with halo (zero padding) ----
    for (int i = tid; i < 36 * 18; i += 256) {
        int row = i / 18;
        int p   = i - row * 18;
        int gy  = gy0 + row - 2;
        int gx  = gx0 + 2 * p - 2;        // even; pair never straddles bounds
        float2 a = make_float2(0.f, 0.f);
        float2 b = make_float2(0.f, 0.f);
        if ((unsigned)gy < HH && (unsigned)gx < WW) {
            const int o = gy * WW + gx;
            a = *reinterpret_cast<const float2*>(Ib + o);
            b = *reinterpret_cast<const float2*>(Jb + o);
        }
        sa[row][p] = a;
        sb[row][p] = b;
    }
    __syncthreads();

    // ---- W blur: 36 rows x 16 out-pairs, products on the fly ----
    const float* saf = reinterpret_cast<const float*>(sa);
    const float* sbf = reinterpret_cast<const float*>(sb);
    for (int i = tid; i < 36 * 16; i += 256) {
        int r = i >> 4;
        int q = i & 15;

        float2 va0 = sa[r][q], va2 = sa[r][q + 1], va4 = sa[r][q + 2];
        float2 vb0 = sb[r][q], vb2 = sb[r][q + 1], vb4 = sb[r][q + 2];
        const int fb = r * (2 * SPITCH) + 2 * q;
        float2 va1 = make_float2(saf[fb + 1], saf[fb + 2]);
        float2 va3 = make_float2(saf[fb + 3], saf[fb + 4]);
        float2 vb1 = make_float2(sbf[fb + 1], sbf[fb + 2]);
        float2 vb3 = make_float2(sbf[fb + 3], sbf[fb + 4]);

        float2 ab0 = mul2(va0, vb0), ab1 = mul2(va1, vb1), ab2 = mul2(va2, vb2),
               ab3 = mul2(va3, vb3), ab4 = mul2(va4, vb4);
        float2 aa0 = mul2(va0, va0), aa1 = mul2(va1, va1), aa2 = mul2(va2, va2),
               aa3 = mul2(va3, va3), aa4 = mul2(va4, va4);
        float2 bb0 = mul2(vb0, vb0), bb1 = mul2(vb1, vb1), bb2 = mul2(vb2, vb2),
               bb3 = mul2(vb3, vb3), bb4 = mul2(vb4, vb4);

        sw[0][r][q] = blur5(va0, va1, va2, va3, va4, w0, w1, w2);
        sw[1][r][q] = blur5(vb0, vb1, vb2, vb3, vb4, w0, w1, w2);
        sw[2][r][q] = blur5(ab0, ab1, ab2, ab3, ab4, w0, w1, w2);
        sw[3][r][q] = blur5(aa0, aa1, aa2, aa3, aa4, w0, w1, w2);
        sw[4][r][q] = blur5(bb0, bb1, bb2, bb3, bb4, w0, w1, w2);
    }
    __syncthreads();

    // ---- H blur: thread owns out-pair column q, y-outputs y0, y0+1 ----
    const int q  = tid & 15;
    const int y0 = (tid >> 4) * 2;

    const size_t obase2 = ((size_t)nd * SLICE) / 2 + (size_t)(gx0 >> 1) + q;

    #pragma unroll
    for (int c = 0; c < 5; c++) {
        float2 t0 = sw[c][y0    ][q];
        float2 t1 = sw[c][y0 + 1][q];
        float2 t2 = sw[c][y0 + 2][q];
        float2 t3 = sw[c][y0 + 3][q];
        float2 t4 = sw[c][y0 + 4][q];
        float2 t5 = sw[c][y0 + 5][q];
        float2 o0 = blur5(t0, t1, t2, t3, t4, w0, w1, w2);
        float2 o1 = blur5(t1, t2, t3, t4, t5, w0, w1, w2);
        const size_t cb = (size_t)c * (TOT / 2) + obase2;
        g_mid2[cb + (size_t)(gy0 + y0)     * (WW / 2)] = __floats2half2_rn(o0.x, o0.y);
        g_mid2[cb + (size_t)(gy0 + y0 + 1) * (WW / 2)] = __floats2half2_rn(o1.x, o1.y);
    }
}

// ---------------------------------------------------------------------------
// Kernel B: D-blur of fp16 mid (4 d-outputs x 4 x-voxels per thread),
// f32x2 accumulation, LNCC + masked reduction + fused final.
// ---------------------------------------------------------------------------
#define P4 (SLICE/4)           // 10752
#define DG (DD/4)              // 40
#define NBLK_B ((NB*DG*P4)/256)  // 3360

__global__ void __launch_bounds__(256) lncc_blur_d_reduce(const float* __restrict__ M,
                                                          float* __restrict__ out)
{
    const int t   = blockIdx.x * 256 + threadIdx.x;
    const int n   = t / (DG * P4);
    const int rem = t - n * (DG * P4);
    const int dg  = rem / P4;
    const int p4  = rem - dg * P4;
    const int d0  = dg * 4;
    const int p   = p4 * 4;

    const float wD[5] = {W0, W1, W2, W1, W0};

    float2 acc[5][4][2];
    #pragma unroll
    for (int c = 0; c < 5; c++)
        #pragma unroll
        for (int k = 0; k < 4; k++) {
            acc[c][k][0] = make_float2(0.f, 0.f);
            acc[c][k][1] = make_float2(0.f, 0.f);
        }

    const size_t pbase  = (size_t)n * VOL + p;
    const size_t pbase2 = pbase / 2;

    #pragma unroll
    for (int c = 0; c < 5; c++) {
        const __half2* __restrict__ ch = g_mid2 + (size_t)c * (TOT / 2) + pbase2;
        #pragma unroll
        for (int ss = 0; ss < 8; ss++) {
            const int s = d0 + ss - 2;
            float2 f01 = make_float2(0.f, 0.f);
            float2 f23 = make_float2(0.f, 0.f);
            if ((unsigned)s < DD) {
                const uint2 raw = *reinterpret_cast<const uint2*>(ch + (size_t)s * (SLICE / 2));
                f01 = __half22float2(*reinterpret_cast<const __half2*>(&raw.x));
                f23 = __half22float2(*reinterpret_cast<const __half2*>(&raw.y));
            }
            #pragma unroll
            for (int k = 0; k < 4; k++) {
                const int j = ss - k;
                if (j >= 0 && j <= 4) {
                    const float2 wj = make_float2(wD[j], wD[j]);
                    acc[c][k][0] = fma2(wj, f01, acc[c][k][0]);
                    acc[c][k][1] = fma2(wj, f23, acc[c][k][1]);
                }
            }
        }
    }

    float sl = 0.f, sm = 0.f;
    #pragma unroll
    for (int k = 0; k < 4; k++) {
        const float4 mk = *reinterpret_cast<const float4*>(
            M + pbase + (size_t)(d0 + k) * SLICE);
        const float mv[4] = {mk.x, mk.y, mk.z, mk.w};
        #pragma unroll
        for (int v = 0; v < 4; v++) {
            const float2* a01 = &acc[0][k][v >> 1];
            float bI  = (v & 1) ? acc[0][k][v >> 1].y : acc[0][k][v >> 1].x;
            float bJ  = (v & 1) ? acc[1][k][v >> 1].y : acc[1][k][v >> 1].x;
            float bIJ = (v & 1) ? acc[2][k][v >> 1].y : acc[2][k][v >> 1].x;
            float bII = (v & 1) ? acc[3][k][v >> 1].y : acc[3][k][v >> 1].x;
            float bJJ = (v & 1) ? acc[4][k][v >> 1].y : acc[4][k][v >> 1].x;
            (void)a01;
            float cross = bIJ - bI * bJ;
            float varI  = fmaxf(bII - bI * bI, 0.f) + 1e-5f;
            float varJ  = fmaxf(bJJ - bJ * bJ, 0.f) + 1e-5f;
            float lncc  = 1.f - cross * rsqrtf(varI * varJ);
            sl += lncc * mv[v];
            sm += mv[v];
        }
    }

    // Block reduction
    #pragma unroll
    for (int o = 16; o > 0; o >>= 1) {
        sl += __shfl_down_sync(0xFFFFFFFFu, sl, o);
        sm += __shfl_down_sync(0xFFFFFFFFu, sm, o);
    }
    __shared__ float rl[8], rm[8];
    const int lane = threadIdx.x & 31, wid = threadIdx.x >> 5;
    if (lane == 0) { rl[wid] = sl; rm[wid] = sm; }
    __syncthreads();
    if (threadIdx.x == 0) {
        float tl = 0.f, tm = 0.f;
        #pragma unroll
        for (int i = 0; i < 8; i++) { tl += rl[i]; tm += rm[i]; }
        atomicAdd(&g_sum[0], (double)tl);
        atomicAdd(&g_sum[1], (double)tm);
        __threadfence();
        const unsigned tk = atomicAdd(&g_ticket, 1u);
        if (tk == (unsigned)(NBLK_B - 1)) {
            const double s0 = atomicAdd(&g_sum[0], 0.0);
            const double s1 = atomicAdd(&g_sum[1], 0.0);
            out[0] = (float)(s0 / (s1 + 1e-8));
        }
    }
}

// ---------------------------------------------------------------------------

extern "C" void kernel_launch(void* const* d_in, const int* in_sizes, int n_in,
                              void* d_out, int out_size)
{
    const float* A = (const float*)d_in[0];  // image_A
    const float* B = (const float*)d_in[1];  // image_B
    const float* M = (const float*)d_in[2];  // mask_A
    float* out = (float*)d_out;

    dim3 gA(WW / 32, HH / 32, NB * DD);      // (7, 6, 320)
    lncc_blur_wh<<<gA, 256>>>(A, B);

    lncc_blur_d_reduce<<<NBLK_B, 256>>>(M, out);
}